// round 15
// baseline (speedup 1.0000x reference)
#include <cuda_runtime.h>
#include <cuda_fp16.h>
#include <cuda_bf16.h>
#include <math.h>
#include <stdint.h>

#define NN 50000
#define EE 800000
#define ETOT (EE + NN)

// ---------------- device scratch ----------------
__device__ __align__(16) __half g_h[NN * 64];    // pre-attention features (fp16 gather payload)
__device__ __align__(16) float g_feat[NN * 64];  // layer output -> next GEMM input (fp32)
__device__ __align__(16) float g_as[NN * 4];
__device__ __align__(16) float g_ad[NN * 4];
__device__ int g_deg[NN];
__device__ int g_rowptr[NN + 1];
__device__ int g_cursor[NN];
__device__ int g_csr[ETOT];

// ---------------- fp32 -> bf16 split ----------------
__device__ __forceinline__ void split2(float x, unsigned short& h, unsigned short& l) {
    __nv_bfloat16 hb = __float2bfloat16(x);
    float lo = x - __bfloat162float(hb);
    __nv_bfloat16 lb = __float2bfloat16(lo);
    h = *(unsigned short*)&hb;
    l = *(unsigned short*)&lb;
}

__device__ __forceinline__ void mma16816(float* c, const uint32_t* a, const uint32_t* b) {
    asm volatile(
        "mma.sync.aligned.m16n8k16.row.col.f32.bf16.bf16.f32 "
        "{%0,%1,%2,%3}, {%4,%5,%6,%7}, {%8,%9}, {%0,%1,%2,%3};"
        : "+f"(c[0]), "+f"(c[1]), "+f"(c[2]), "+f"(c[3])
        : "r"(a[0]), "r"(a[1]), "r"(a[2]), "r"(a[3]), "r"(b[0]), "r"(b[1]));
}

// ---------------- tensor GEMM: C[n,FOUT](fp16) = X[n,FIN](fp32) @ W[FIN,FOUT] ----------------
// Dual bf16 layout [xh|xl]; 3-pass MMA (Ah@Bh + Al@Bh + Ah@Bl).
// Register-prefetch pipeline: chunk ch+1 LDGs issued before MMA(ch), hidden under compute.
// AMODE: 0=none, 1=4-head alpha epilogue (FOUT=64), 2=1-head alpha epilogue (FOUT=40).
template <int FIN, int FOUT, int AMODE>
__global__ void __launch_bounds__(256, 2) mma_gemm(
    const float* __restrict__ X, const float* __restrict__ W,
    __half* __restrict__ C, const float* __restrict__ asrc,
    const float* __restrict__ adst) {
    constexpr int KC = 32;
    constexpr int NCH = FIN / KC;      // 8 or 2
    constexpr int PITCH = 72;
    constexpr int NT = FOUT / 8;       // 8 or 5
    constexpr int NB4 = KC * FOUT / 4; // 512 or 320

    __shared__ unsigned short As[128 * PITCH];
    __shared__ unsigned short Bs[FOUT * PITCH];

    const int tid = threadIdx.x;
    const int wid = tid >> 5, lane = tid & 31;
    const int r4 = lane >> 2;
    const int c2 = (lane & 3) * 2;
    const int rowBase = blockIdx.x * 128;
    const int wm = wid * 16;

    float acc[NT][4];
#pragma unroll
    for (int t = 0; t < NT; t++)
#pragma unroll
        for (int j = 0; j < 4; j++) acc[t][j] = 0.f;

    float4 av[4], bv[2];
    auto ldA = [&](int ch) {
#pragma unroll
        for (int it = 0; it < 4; it++) {
            int idx = tid + it * 256;
            int r = idx >> 3, c4 = idx & 7;
            int row = rowBase + r;
            av[it] = (row < NN) ? *(const float4*)(X + (size_t)row * FIN + ch * KC + c4 * 4)
                                : make_float4(0.f, 0.f, 0.f, 0.f);
        }
    };
    auto ldB = [&](int ch) {
#pragma unroll
        for (int it = 0; it < 2; it++) {
            int idx = tid + it * 256;
            if (idx < NB4) {
                int k = idx / (FOUT / 4), n4 = idx % (FOUT / 4);
                bv[it] = __ldg((const float4*)(W + (size_t)(ch * KC + k) * FOUT) + n4);
            }
        }
    };

    ldA(0);
    ldB(0);

    for (int ch = 0; ch < NCH; ch++) {
        __syncthreads();
        // ---- store prefetched A regs -> smem (split) ----
#pragma unroll
        for (int it = 0; it < 4; it++) {
            int idx = tid + it * 256;
            int r = idx >> 3, c4 = idx & 7;
            float vv[4] = {av[it].x, av[it].y, av[it].z, av[it].w};
            unsigned short hs[4], ls[4];
#pragma unroll
            for (int j = 0; j < 4; j++) split2(vv[j], hs[j], ls[j]);
            *(uint2*)(As + r * PITCH + c4 * 4) = *(uint2*)hs;
            *(uint2*)(As + r * PITCH + 32 + c4 * 4) = *(uint2*)ls;
        }
        // ---- store prefetched B regs -> smem (split, transposed) ----
#pragma unroll
        for (int it = 0; it < 2; it++) {
            int idx = tid + it * 256;
            if (idx < NB4) {
                int k = idx / (FOUT / 4), n4 = idx % (FOUT / 4);
                float vv[4] = {bv[it].x, bv[it].y, bv[it].z, bv[it].w};
#pragma unroll
                for (int j = 0; j < 4; j++) {
                    unsigned short h, l;
                    split2(vv[j], h, l);
                    Bs[(n4 * 4 + j) * PITCH + k] = h;
                    Bs[(n4 * 4 + j) * PITCH + 32 + k] = l;
                }
            }
        }
        __syncthreads();

        // ---- prefetch next chunk (LDG latency hidden under MMA below) ----
        if (ch + 1 < NCH) { ldA(ch + 1); ldB(ch + 1); }

        // ---- MMA: 2 k-steps of 16 per half ----
#pragma unroll
        for (int ks = 0; ks < 2; ks++) {
            int kb = ks * 16 + c2;
            uint32_t ah[4], al[4];
            ah[0] = *(const uint32_t*)(As + (wm + r4) * PITCH + kb);
            ah[1] = *(const uint32_t*)(As + (wm + r4 + 8) * PITCH + kb);
            ah[2] = *(const uint32_t*)(As + (wm + r4) * PITCH + kb + 8);
            ah[3] = *(const uint32_t*)(As + (wm + r4 + 8) * PITCH + kb + 8);
            al[0] = *(const uint32_t*)(As + (wm + r4) * PITCH + 32 + kb);
            al[1] = *(const uint32_t*)(As + (wm + r4 + 8) * PITCH + 32 + kb);
            al[2] = *(const uint32_t*)(As + (wm + r4) * PITCH + 32 + kb + 8);
            al[3] = *(const uint32_t*)(As + (wm + r4 + 8) * PITCH + 32 + kb + 8);
#pragma unroll
            for (int t = 0; t < NT; t++) {
                uint32_t bh[2], bl[2];
                bh[0] = *(const uint32_t*)(Bs + (t * 8 + r4) * PITCH + kb);
                bh[1] = *(const uint32_t*)(Bs + (t * 8 + r4) * PITCH + kb + 8);
                bl[0] = *(const uint32_t*)(Bs + (t * 8 + r4) * PITCH + 32 + kb);
                bl[1] = *(const uint32_t*)(Bs + (t * 8 + r4) * PITCH + 32 + kb + 8);
                mma16816(acc[t], ah, bh);
                mma16816(acc[t], al, bh);
                mma16816(acc[t], ah, bl);
            }
        }
    }

    // ---- epilogue: fp16 C stores ----
    int ra = rowBase + wm + r4;
    int rb = ra + 8;
#pragma unroll
    for (int t = 0; t < NT; t++) {
        int col = t * 8 + c2;
        if (ra < NN) {
            __half2 p = __floats2half2_rn(acc[t][0], acc[t][1]);
            *(__half2*)(C + (size_t)ra * FOUT + col) = p;
        }
        if (rb < NN) {
            __half2 p = __floats2half2_rn(acc[t][2], acc[t][3]);
            *(__half2*)(C + (size_t)rb * FOUT + col) = p;
        }
    }
    if (AMODE == 1) {
#pragma unroll
        for (int h = 0; h < 4; h++) {
            float pa_s = 0.f, pa_d = 0.f, pb_s = 0.f, pb_d = 0.f;
#pragma unroll
            for (int tt = 0; tt < 2; tt++) {
                int t = 2 * h + tt;
#pragma unroll
                for (int j = 0; j < 2; j++) {
                    int col = t * 8 + c2 + j;
                    float as_v = __ldg(asrc + col);
                    float ad_v = __ldg(adst + col);
                    pa_s += acc[t][j] * as_v;     pa_d += acc[t][j] * ad_v;
                    pb_s += acc[t][2 + j] * as_v; pb_d += acc[t][2 + j] * ad_v;
                }
            }
            pa_s += __shfl_xor_sync(0xffffffffu, pa_s, 1);
            pa_s += __shfl_xor_sync(0xffffffffu, pa_s, 2);
            pa_d += __shfl_xor_sync(0xffffffffu, pa_d, 1);
            pa_d += __shfl_xor_sync(0xffffffffu, pa_d, 2);
            pb_s += __shfl_xor_sync(0xffffffffu, pb_s, 1);
            pb_s += __shfl_xor_sync(0xffffffffu, pb_s, 2);
            pb_d += __shfl_xor_sync(0xffffffffu, pb_d, 1);
            pb_d += __shfl_xor_sync(0xffffffffu, pb_d, 2);
            if ((lane & 3) == 0) {
                if (ra < NN) { g_as[ra * 4 + h] = pa_s; g_ad[ra * 4 + h] = pa_d; }
                if (rb < NN) { g_as[rb * 4 + h] = pb_s; g_ad[rb * 4 + h] = pb_d; }
            }
        }
    }
    if (AMODE == 2) {
        float pa_s = 0.f, pa_d = 0.f, pb_s = 0.f, pb_d = 0.f;
#pragma unroll
        for (int t = 0; t < NT; t++) {
#pragma unroll
            for (int j = 0; j < 2; j++) {
                int col = t * 8 + c2 + j;
                float as_v = __ldg(asrc + col);
                float ad_v = __ldg(adst + col);
                pa_s += acc[t][j] * as_v;     pa_d += acc[t][j] * ad_v;
                pb_s += acc[t][2 + j] * as_v; pb_d += acc[t][2 + j] * ad_v;
            }
        }
        pa_s += __shfl_xor_sync(0xffffffffu, pa_s, 1);
        pa_s += __shfl_xor_sync(0xffffffffu, pa_s, 2);
        pa_d += __shfl_xor_sync(0xffffffffu, pa_d, 1);
        pa_d += __shfl_xor_sync(0xffffffffu, pa_d, 2);
        pb_s += __shfl_xor_sync(0xffffffffu, pb_s, 1);
        pb_s += __shfl_xor_sync(0xffffffffu, pb_s, 2);
        pb_d += __shfl_xor_sync(0xffffffffu, pb_d, 1);
        pb_d += __shfl_xor_sync(0xffffffffu, pb_d, 2);
        if ((lane & 3) == 0) {
            if (ra < NN) { g_as[ra] = pa_s; g_ad[ra] = pa_d; }
            if (rb < NN) { g_as[rb] = pb_s; g_ad[rb] = pb_d; }
        }
    }
}

// ---------------- CSR construction ----------------
__global__ void hist_kernel(const int* __restrict__ dsts) {
    int e = blockIdx.x * blockDim.x + threadIdx.x;
    if (e >= ETOT) return;
    int d = (e < EE) ? __ldg(dsts + e) : (e - EE);
    atomicAdd(&g_deg[d], 1);
}

__global__ void scan_kernel() {
    __shared__ int sums[1024];
    const int t = threadIdx.x;
    constexpr int CH = (NN + 1 + 1023) / 1024;
    const int base = t * CH;
    int s = 0;
    for (int j = 0; j < CH; j++) {
        int idx = base + j;
        if (idx < NN) s += g_deg[idx];
    }
    sums[t] = s;
    __syncthreads();
    for (int off = 1; off < 1024; off <<= 1) {
        int v = (t >= off) ? sums[t - off] : 0;
        __syncthreads();
        sums[t] += v;
        __syncthreads();
    }
    int run = (t == 0) ? 0 : sums[t - 1];
    for (int j = 0; j < CH; j++) {
        int idx = base + j;
        if (idx <= NN) {
            g_rowptr[idx] = run;
            if (idx < NN) {
                g_cursor[idx] = run;
                run += g_deg[idx];
            }
        }
    }
}

__global__ void fill_kernel(const int* __restrict__ srcs, const int* __restrict__ dsts) {
    int e = blockIdx.x * blockDim.x + threadIdx.x;
    if (e >= ETOT) return;
    int s, d;
    if (e < EE) { s = __ldg(srcs + e); d = __ldg(dsts + e); }
    else        { s = d = e - EE; }
    int pos = atomicAdd(&g_cursor[d], 1);
    g_csr[pos] = s;
}

// ---------------- aggregate (layers 1-2): fp16 gather, fp32 out + relu ----------------
__global__ void agg_mid_kernel(const __half* __restrict__ h, const float* __restrict__ bias,
                               float* __restrict__ dest) {
    int gt = blockIdx.x * blockDim.x + threadIdx.x;
    int n = gt >> 4;
    int q = gt & 15;
    if (n >= NN) return;
    int hh = q >> 2;

    const float ad = g_ad[n * 4 + hh];
    const int beg = __ldg(g_rowptr + n);
    const int end = __ldg(g_rowptr + n + 1);

    float4 acc = make_float4(0.f, 0.f, 0.f, 0.f);
    float den = 0.f;
    for (int i = beg; i < end; i++) {
        int s = __ldg(g_csr + i);
        float v = __ldg(g_as + s * 4 + hh) + ad;
        v = v > 0.f ? v : 0.2f * v;
        float w = __expf(v);
        den += w;
        uint2 u = __ldg((const uint2*)(h + (size_t)s * 64) + q);
        float2 f01 = __half22float2(*(__half2*)&u.x);
        float2 f23 = __half22float2(*(__half2*)&u.y);
        acc.x += w * f01.x; acc.y += w * f01.y;
        acc.z += w * f23.x; acc.w += w * f23.y;
    }
    float inv = 1.f / (den + 1e-16f);
    float4 b = __ldg((const float4*)bias + q);
    float4 o;
    o.x = acc.x * inv + b.x; o.y = acc.y * inv + b.y;
    o.z = acc.z * inv + b.z; o.w = acc.w * inv + b.w;
    o.x = o.x > 0.f ? o.x : 0.f;
    o.y = o.y > 0.f ? o.y : 0.f;
    o.z = o.z > 0.f ? o.z : 0.f;
    o.w = o.w > 0.f ? o.w : 0.f;
    *(float4*)(dest + (size_t)n * 64 + q * 4) = o;
}

// ---------------- aggregate (layer 3): fp16 gather, fp32 out ----------------
__global__ void agg_out_kernel(const __half* __restrict__ h, const float* __restrict__ bias,
                               float* __restrict__ dest) {
    int gt = blockIdx.x * blockDim.x + threadIdx.x;
    int n = gt >> 4;
    int q = gt & 15;
    if (n >= NN) return;

    const float ad = g_ad[n];
    const int beg = __ldg(g_rowptr + n);
    const int end = __ldg(g_rowptr + n + 1);

    float4 acc = make_float4(0.f, 0.f, 0.f, 0.f);
    float den = 0.f;
    for (int i = beg; i < end; i++) {
        int s = __ldg(g_csr + i);
        float v = __ldg(g_as + s) + ad;
        v = v > 0.f ? v : 0.2f * v;
        float w = __expf(v);
        den += w;
        if (q < 10) {
            uint2 u = __ldg((const uint2*)(h + (size_t)s * 40) + q);
            float2 f01 = __half22float2(*(__half2*)&u.x);
            float2 f23 = __half22float2(*(__half2*)&u.y);
            acc.x += w * f01.x; acc.y += w * f01.y;
            acc.z += w * f23.x; acc.w += w * f23.y;
        }
    }
    if (q < 10) {
        float inv = 1.f / (den + 1e-16f);
        float4 b = __ldg((const float4*)bias + q);
        float4 o;
        o.x = acc.x * inv + b.x; o.y = acc.y * inv + b.y;
        o.z = acc.z * inv + b.z; o.w = acc.w * inv + b.w;
        *(float4*)(dest + (size_t)n * 40 + q * 4) = o;
    }
}

// ---------------- launch ----------------
extern "C" void kernel_launch(void* const* d_in, const int* in_sizes, int n_in,
                              void* d_out, int out_size) {
    const float* x = (const float*)d_in[0];
    const int* ei = (const int*)d_in[1];    // int32 (JAX x64 disabled)
    const float* W1 = (const float*)d_in[2];
    const float* asr1 = (const float*)d_in[3];
    const float* adr1 = (const float*)d_in[4];
    const float* b1 = (const float*)d_in[5];
    const float* W2 = (const float*)d_in[6];
    const float* asr2 = (const float*)d_in[7];
    const float* adr2 = (const float*)d_in[8];
    const float* b2 = (const float*)d_in[9];
    const float* W3 = (const float*)d_in[10];
    const float* asr3 = (const float*)d_in[11];
    const float* adr3 = (const float*)d_in[12];
    const float* b3 = (const float*)d_in[13];
    float* out = (float*)d_out;

    const int* esrc = ei;
    const int* edst = ei + EE;

    __half* p_h;
    float* p_feat;
    void* p_deg;
    cudaGetSymbolAddress((void**)&p_h, g_h);
    cudaGetSymbolAddress((void**)&p_feat, g_feat);
    cudaGetSymbolAddress(&p_deg, g_deg);

    const int mmaGrid = (NN + 127) / 128;  // 391
    const int edgeGrid = (ETOT + 255) / 256;
    const int aggGrid = (NN * 16 + 255) / 256;

    // Fork: CSR build on a side stream, overlapped with layer-1 GEMM.
    cudaStream_t s2;
    cudaStreamCreateWithFlags(&s2, cudaStreamNonBlocking);
    cudaEvent_t evFork, evJoin;
    cudaEventCreateWithFlags(&evFork, cudaEventDisableTiming);
    cudaEventCreateWithFlags(&evJoin, cudaEventDisableTiming);

    cudaEventRecord(evFork, 0);
    cudaStreamWaitEvent(s2, evFork, 0);
    cudaMemsetAsync(p_deg, 0, NN * sizeof(int), s2);
    hist_kernel<<<edgeGrid, 256, 0, s2>>>(edst);
    scan_kernel<<<1, 1024, 0, s2>>>();
    fill_kernel<<<edgeGrid, 256, 0, s2>>>(esrc, edst);
    cudaEventRecord(evJoin, s2);

    // ---------------- layer 1: 256 -> 4x16 ----------------
    mma_gemm<256, 64, 1><<<mmaGrid, 256>>>(x, W1, p_h, asr1, adr1);
    cudaStreamWaitEvent(0, evJoin, 0);
    agg_mid_kernel<<<aggGrid, 256>>>(p_h, b1, p_feat);

    // ---------------- layer 2: 64 -> 4x16 ----------------
    mma_gemm<64, 64, 1><<<mmaGrid, 256>>>(p_feat, W2, p_h, asr2, adr2);
    agg_mid_kernel<<<aggGrid, 256>>>(p_h, b2, p_feat);

    // ---------------- layer 3: 64 -> 1x40 (alpha fused, no prep kernel) ----------------
    mma_gemm<64, 40, 2><<<mmaGrid, 256>>>(p_feat, W3, p_h, asr3, adr3);
    agg_out_kernel<<<aggGrid, 256>>>(p_h, b3, out);
}

// round 16
// speedup vs baseline: 1.1476x; 1.1476x over previous
#include <cuda_runtime.h>
#include <cuda_fp16.h>
#include <cuda_bf16.h>
#include <math.h>
#include <stdint.h>

#define NN 50000
#define EE 800000
#define ETOT (EE + NN)

// ---------------- device scratch ----------------
__device__ __align__(16) __half g_h[NN * 64];    // pre-attention features (fp16 gather payload)
__device__ __align__(16) float g_feat[NN * 64];  // layer output -> next GEMM input (fp32)
__device__ __align__(16) float g_as[NN * 4];
__device__ __align__(16) float g_ad[NN * 4];
__device__ int g_deg[NN];
__device__ int g_rowptr[NN + 1];
__device__ int g_cursor[NN];
__device__ int g_csr[ETOT];

// ---------------- fp32 -> bf16 split ----------------
__device__ __forceinline__ void split2(float x, unsigned short& h, unsigned short& l) {
    __nv_bfloat16 hb = __float2bfloat16(x);
    float lo = x - __bfloat162float(hb);
    __nv_bfloat16 lb = __float2bfloat16(lo);
    h = *(unsigned short*)&hb;
    l = *(unsigned short*)&lb;
}

__device__ __forceinline__ void mma16816(float* c, const uint32_t* a, const uint32_t* b) {
    asm volatile(
        "mma.sync.aligned.m16n8k16.row.col.f32.bf16.bf16.f32 "
        "{%0,%1,%2,%3}, {%4,%5,%6,%7}, {%8,%9}, {%0,%1,%2,%3};"
        : "+f"(c[0]), "+f"(c[1]), "+f"(c[2]), "+f"(c[3])
        : "r"(a[0]), "r"(a[1]), "r"(a[2]), "r"(a[3]), "r"(b[0]), "r"(b[1]));
}

// ---------------- tensor GEMM (R14 body): C[n,FOUT](fp16) = X @ W ----------------
// Dual bf16 layout [xh|xl]; 3-pass MMA (Ah@Bh + Al@Bh + Ah@Bl).
// AMODE: 0=none, 1=4-head alpha epilogue (FOUT=64), 2=1-head alpha epilogue (FOUT=40).
template <int FIN, int FOUT, int AMODE>
__global__ void __launch_bounds__(256, 3) mma_gemm(
    const float* __restrict__ X, const float* __restrict__ W,
    __half* __restrict__ C, const float* __restrict__ asrc,
    const float* __restrict__ adst) {
    constexpr int KC = 32;
    constexpr int NCH = FIN / KC;
    constexpr int PITCH = 72;
    constexpr int NT = FOUT / 8;

    __shared__ unsigned short As[128 * PITCH];
    __shared__ unsigned short Bs[FOUT * PITCH];

    const int tid = threadIdx.x;
    const int wid = tid >> 5, lane = tid & 31;
    const int r4 = lane >> 2;
    const int c2 = (lane & 3) * 2;
    const int rowBase = blockIdx.x * 128;
    const int wm = wid * 16;

    float acc[NT][4];
#pragma unroll
    for (int t = 0; t < NT; t++)
#pragma unroll
        for (int j = 0; j < 4; j++) acc[t][j] = 0.f;

    for (int ch = 0; ch < NCH; ch++) {
        __syncthreads();
        for (int idx = tid; idx < 128 * (KC / 4); idx += 256) {
            int r = idx >> 3, c4 = idx & 7;
            int row = rowBase + r;
            float4 v = make_float4(0.f, 0.f, 0.f, 0.f);
            if (row < NN) v = *(const float4*)(X + (size_t)row * FIN + ch * KC + c4 * 4);
            float vv[4] = {v.x, v.y, v.z, v.w};
            unsigned short hs[4], ls[4];
#pragma unroll
            for (int j = 0; j < 4; j++) split2(vv[j], hs[j], ls[j]);
            *(uint2*)(As + r * PITCH + c4 * 4) = *(uint2*)hs;
            *(uint2*)(As + r * PITCH + 32 + c4 * 4) = *(uint2*)ls;
        }
        for (int idx = tid; idx < KC * FOUT; idx += 256) {
            int k = idx / FOUT, n = idx % FOUT;
            unsigned short h, l;
            split2(__ldg(W + (size_t)(ch * KC + k) * FOUT + n), h, l);
            Bs[n * PITCH + k] = h;
            Bs[n * PITCH + 32 + k] = l;
        }
        __syncthreads();

#pragma unroll
        for (int ks = 0; ks < 2; ks++) {
            int kb = ks * 16 + c2;
            uint32_t ah[4], al[4];
            ah[0] = *(const uint32_t*)(As + (wm + r4) * PITCH + kb);
            ah[1] = *(const uint32_t*)(As + (wm + r4 + 8) * PITCH + kb);
            ah[2] = *(const uint32_t*)(As + (wm + r4) * PITCH + kb + 8);
            ah[3] = *(const uint32_t*)(As + (wm + r4 + 8) * PITCH + kb + 8);
            al[0] = *(const uint32_t*)(As + (wm + r4) * PITCH + 32 + kb);
            al[1] = *(const uint32_t*)(As + (wm + r4 + 8) * PITCH + 32 + kb);
            al[2] = *(const uint32_t*)(As + (wm + r4) * PITCH + 32 + kb + 8);
            al[3] = *(const uint32_t*)(As + (wm + r4 + 8) * PITCH + 32 + kb + 8);
#pragma unroll
            for (int t = 0; t < NT; t++) {
                uint32_t bh[2], bl[2];
                bh[0] = *(const uint32_t*)(Bs + (t * 8 + r4) * PITCH + kb);
                bh[1] = *(const uint32_t*)(Bs + (t * 8 + r4) * PITCH + kb + 8);
                bl[0] = *(const uint32_t*)(Bs + (t * 8 + r4) * PITCH + 32 + kb);
                bl[1] = *(const uint32_t*)(Bs + (t * 8 + r4) * PITCH + 32 + kb + 8);
                mma16816(acc[t], ah, bh);
                mma16816(acc[t], al, bh);
                mma16816(acc[t], ah, bl);
            }
        }
    }

    int ra = rowBase + wm + r4;
    int rb = ra + 8;
#pragma unroll
    for (int t = 0; t < NT; t++) {
        int col = t * 8 + c2;
        if (ra < NN) {
            __half2 p = __floats2half2_rn(acc[t][0], acc[t][1]);
            *(__half2*)(C + (size_t)ra * FOUT + col) = p;
        }
        if (rb < NN) {
            __half2 p = __floats2half2_rn(acc[t][2], acc[t][3]);
            *(__half2*)(C + (size_t)rb * FOUT + col) = p;
        }
    }
    if (AMODE == 1) {
#pragma unroll
        for (int h = 0; h < 4; h++) {
            float pa_s = 0.f, pa_d = 0.f, pb_s = 0.f, pb_d = 0.f;
#pragma unroll
            for (int tt = 0; tt < 2; tt++) {
                int t = 2 * h + tt;
#pragma unroll
                for (int j = 0; j < 2; j++) {
                    int col = t * 8 + c2 + j;
                    float as_v = __ldg(asrc + col);
                    float ad_v = __ldg(adst + col);
                    pa_s += acc[t][j] * as_v;     pa_d += acc[t][j] * ad_v;
                    pb_s += acc[t][2 + j] * as_v; pb_d += acc[t][2 + j] * ad_v;
                }
            }
            pa_s += __shfl_xor_sync(0xffffffffu, pa_s, 1);
            pa_s += __shfl_xor_sync(0xffffffffu, pa_s, 2);
            pa_d += __shfl_xor_sync(0xffffffffu, pa_d, 1);
            pa_d += __shfl_xor_sync(0xffffffffu, pa_d, 2);
            pb_s += __shfl_xor_sync(0xffffffffu, pb_s, 1);
            pb_s += __shfl_xor_sync(0xffffffffu, pb_s, 2);
            pb_d += __shfl_xor_sync(0xffffffffu, pb_d, 1);
            pb_d += __shfl_xor_sync(0xffffffffu, pb_d, 2);
            if ((lane & 3) == 0) {
                if (ra < NN) { g_as[ra * 4 + h] = pa_s; g_ad[ra * 4 + h] = pa_d; }
                if (rb < NN) { g_as[rb * 4 + h] = pb_s; g_ad[rb * 4 + h] = pb_d; }
            }
        }
    }
    if (AMODE == 2) {
        float pa_s = 0.f, pa_d = 0.f, pb_s = 0.f, pb_d = 0.f;
#pragma unroll
        for (int t = 0; t < NT; t++) {
#pragma unroll
            for (int j = 0; j < 2; j++) {
                int col = t * 8 + c2 + j;
                float as_v = __ldg(asrc + col);
                float ad_v = __ldg(adst + col);
                pa_s += acc[t][j] * as_v;     pa_d += acc[t][j] * ad_v;
                pb_s += acc[t][2 + j] * as_v; pb_d += acc[t][2 + j] * ad_v;
            }
        }
        pa_s += __shfl_xor_sync(0xffffffffu, pa_s, 1);
        pa_s += __shfl_xor_sync(0xffffffffu, pa_s, 2);
        pa_d += __shfl_xor_sync(0xffffffffu, pa_d, 1);
        pa_d += __shfl_xor_sync(0xffffffffu, pa_d, 2);
        pb_s += __shfl_xor_sync(0xffffffffu, pb_s, 1);
        pb_s += __shfl_xor_sync(0xffffffffu, pb_s, 2);
        pb_d += __shfl_xor_sync(0xffffffffu, pb_d, 1);
        pb_d += __shfl_xor_sync(0xffffffffu, pb_d, 2);
        if ((lane & 3) == 0) {
            if (ra < NN) { g_as[ra] = pa_s; g_ad[ra] = pa_d; }
            if (rb < NN) { g_as[rb] = pb_s; g_ad[rb] = pb_d; }
        }
    }
}

// ---------------- CSR construction ----------------
__global__ void hist_kernel(const int* __restrict__ dsts) {
    int e = blockIdx.x * blockDim.x + threadIdx.x;
    if (e >= ETOT) return;
    int d = (e < EE) ? __ldg(dsts + e) : (e - EE);
    atomicAdd(&g_deg[d], 1);
}

__global__ void scan_kernel() {
    __shared__ int sums[1024];
    const int t = threadIdx.x;
    constexpr int CH = (NN + 1 + 1023) / 1024;
    const int base = t * CH;
    int s = 0;
    for (int j = 0; j < CH; j++) {
        int idx = base + j;
        if (idx < NN) s += g_deg[idx];
    }
    sums[t] = s;
    __syncthreads();
    for (int off = 1; off < 1024; off <<= 1) {
        int v = (t >= off) ? sums[t - off] : 0;
        __syncthreads();
        sums[t] += v;
        __syncthreads();
    }
    int run = (t == 0) ? 0 : sums[t - 1];
    for (int j = 0; j < CH; j++) {
        int idx = base + j;
        if (idx <= NN) {
            g_rowptr[idx] = run;
            if (idx < NN) {
                g_cursor[idx] = run;
                run += g_deg[idx];
            }
        }
    }
}

__global__ void fill_kernel(const int* __restrict__ srcs, const int* __restrict__ dsts) {
    int e = blockIdx.x * blockDim.x + threadIdx.x;
    if (e >= ETOT) return;
    int s, d;
    if (e < EE) { s = __ldg(srcs + e); d = __ldg(dsts + e); }
    else        { s = d = e - EE; }
    int pos = atomicAdd(&g_cursor[d], 1);
    g_csr[pos] = s;
}

// ---------------- aggregate (layers 1-2): warp per node, 2 edge slots ----------------
__global__ void agg_mid_kernel(const __half* __restrict__ h, const float* __restrict__ bias,
                               float* __restrict__ dest) {
    int gt = blockIdx.x * blockDim.x + threadIdx.x;
    int n = gt >> 5;                       // one warp per node
    int half = (threadIdx.x >> 4) & 1;     // edge slot 0/1
    int q = threadIdx.x & 15;              // feature float4 index
    if (n >= NN) return;
    int hh = q >> 2;

    const float ad = g_ad[n * 4 + hh];
    const int beg = __ldg(g_rowptr + n);
    const int end = __ldg(g_rowptr + n + 1);

    float4 acc = make_float4(0.f, 0.f, 0.f, 0.f);
    float den = 0.f;
    for (int i = beg + half; i < end; i += 2) {
        int s = __ldg(g_csr + i);
        float v = __ldg(g_as + s * 4 + hh) + ad;
        v = v > 0.f ? v : 0.2f * v;
        float w = __expf(v);
        den += w;
        uint2 u = __ldg((const uint2*)(h + (size_t)s * 64) + q);
        float2 f01 = __half22float2(*(__half2*)&u.x);
        float2 f23 = __half22float2(*(__half2*)&u.y);
        acc.x += w * f01.x; acc.y += w * f01.y;
        acc.z += w * f23.x; acc.w += w * f23.y;
    }
    // cross-half reduction (slot 0 + slot 1)
    acc.x += __shfl_xor_sync(0xffffffffu, acc.x, 16);
    acc.y += __shfl_xor_sync(0xffffffffu, acc.y, 16);
    acc.z += __shfl_xor_sync(0xffffffffu, acc.z, 16);
    acc.w += __shfl_xor_sync(0xffffffffu, acc.w, 16);
    den += __shfl_xor_sync(0xffffffffu, den, 16);

    if (half == 0) {
        float inv = 1.f / (den + 1e-16f);
        float4 b = __ldg((const float4*)bias + q);
        float4 o;
        o.x = acc.x * inv + b.x; o.y = acc.y * inv + b.y;
        o.z = acc.z * inv + b.z; o.w = acc.w * inv + b.w;
        o.x = o.x > 0.f ? o.x : 0.f;
        o.y = o.y > 0.f ? o.y : 0.f;
        o.z = o.z > 0.f ? o.z : 0.f;
        o.w = o.w > 0.f ? o.w : 0.f;
        *(float4*)(dest + (size_t)n * 64 + q * 4) = o;
    }
}

// ---------------- aggregate (layer 3): warp per node, 2 edge slots ----------------
__global__ void agg_out_kernel(const __half* __restrict__ h, const float* __restrict__ bias,
                               float* __restrict__ dest) {
    int gt = blockIdx.x * blockDim.x + threadIdx.x;
    int n = gt >> 5;
    int half = (threadIdx.x >> 4) & 1;
    int q = threadIdx.x & 15;
    if (n >= NN) return;

    const float ad = g_ad[n];
    const int beg = __ldg(g_rowptr + n);
    const int end = __ldg(g_rowptr + n + 1);

    float4 acc = make_float4(0.f, 0.f, 0.f, 0.f);
    float den = 0.f;
    for (int i = beg + half; i < end; i += 2) {
        int s = __ldg(g_csr + i);
        float v = __ldg(g_as + s) + ad;
        v = v > 0.f ? v : 0.2f * v;
        float w = __expf(v);
        den += w;
        if (q < 10) {
            uint2 u = __ldg((const uint2*)(h + (size_t)s * 40) + q);
            float2 f01 = __half22float2(*(__half2*)&u.x);
            float2 f23 = __half22float2(*(__half2*)&u.y);
            acc.x += w * f01.x; acc.y += w * f01.y;
            acc.z += w * f23.x; acc.w += w * f23.y;
        }
    }
    acc.x += __shfl_xor_sync(0xffffffffu, acc.x, 16);
    acc.y += __shfl_xor_sync(0xffffffffu, acc.y, 16);
    acc.z += __shfl_xor_sync(0xffffffffu, acc.z, 16);
    acc.w += __shfl_xor_sync(0xffffffffu, acc.w, 16);
    den += __shfl_xor_sync(0xffffffffu, den, 16);

    if (half == 0 && q < 10) {
        float inv = 1.f / (den + 1e-16f);
        float4 b = __ldg((const float4*)bias + q);
        float4 o;
        o.x = acc.x * inv + b.x; o.y = acc.y * inv + b.y;
        o.z = acc.z * inv + b.z; o.w = acc.w * inv + b.w;
        *(float4*)(dest + (size_t)n * 40 + q * 4) = o;
    }
}

// ---------------- launch ----------------
extern "C" void kernel_launch(void* const* d_in, const int* in_sizes, int n_in,
                              void* d_out, int out_size) {
    const float* x = (const float*)d_in[0];
    const int* ei = (const int*)d_in[1];    // int32 (JAX x64 disabled)
    const float* W1 = (const float*)d_in[2];
    const float* asr1 = (const float*)d_in[3];
    const float* adr1 = (const float*)d_in[4];
    const float* b1 = (const float*)d_in[5];
    const float* W2 = (const float*)d_in[6];
    const float* asr2 = (const float*)d_in[7];
    const float* adr2 = (const float*)d_in[8];
    const float* b2 = (const float*)d_in[9];
    const float* W3 = (const float*)d_in[10];
    const float* asr3 = (const float*)d_in[11];
    const float* adr3 = (const float*)d_in[12];
    const float* b3 = (const float*)d_in[13];
    float* out = (float*)d_out;

    const int* esrc = ei;
    const int* edst = ei + EE;

    __half* p_h;
    float* p_feat;
    void* p_deg;
    cudaGetSymbolAddress((void**)&p_h, g_h);
    cudaGetSymbolAddress((void**)&p_feat, g_feat);
    cudaGetSymbolAddress(&p_deg, g_deg);

    const int mmaGrid = (NN + 127) / 128;  // 391
    const int edgeGrid = (ETOT + 255) / 256;
    const int aggGrid = (NN * 32 + 255) / 256;  // warp per node

    // Fork: CSR build on a side stream, overlapped with layer-1 GEMM.
    cudaStream_t s2;
    cudaStreamCreateWithFlags(&s2, cudaStreamNonBlocking);
    cudaEvent_t evFork, evJoin;
    cudaEventCreateWithFlags(&evFork, cudaEventDisableTiming);
    cudaEventCreateWithFlags(&evJoin, cudaEventDisableTiming);

    cudaEventRecord(evFork, 0);
    cudaStreamWaitEvent(s2, evFork, 0);
    cudaMemsetAsync(p_deg, 0, NN * sizeof(int), s2);
    hist_kernel<<<edgeGrid, 256, 0, s2>>>(edst);
    scan_kernel<<<1, 1024, 0, s2>>>();
    fill_kernel<<<edgeGrid, 256, 0, s2>>>(esrc, edst);
    cudaEventRecord(evJoin, s2);

    // ---------------- layer 1: 256 -> 4x16 ----------------
    mma_gemm<256, 64, 1><<<mmaGrid, 256>>>(x, W1, p_h, asr1, adr1);
    cudaStreamWaitEvent(0, evJoin, 0);
    agg_mid_kernel<<<aggGrid, 256>>>(p_h, b1, p_feat);

    // ---------------- layer 2: 64 -> 4x16 ----------------
    mma_gemm<64, 64, 1><<<mmaGrid, 256>>>(p_feat, W2, p_h, asr2, adr2);
    agg_mid_kernel<<<aggGrid, 256>>>(p_h, b2, p_feat);

    // ---------------- layer 3: 64 -> 1x40 (alpha fused in GEMM epilogue) ----------------
    mma_gemm<64, 40, 2><<<mmaGrid, 256>>>(p_feat, W3, p_h, asr3, adr3);
    agg_out_kernel<<<aggGrid, 256>>>(p_h, b3, out);
}